// round 2
// baseline (speedup 1.0000x reference)
#include <cuda_runtime.h>

// out[b,k] = tanh( sum_n W[k,n] * x[b,k,n] )
// B=64, K=4096, N=256 (fp32). One warp per TWO consecutive (b,k) outputs.
// 8 front-batched float4 loads per warp-iteration (deep MLP), x loaded with
// streaming hint (evict-first) so the 4MB W stays L2-resident.

#define GK 4096
#define GN 256

__device__ __forceinline__ float4 ldcs4(const float4* p) {
    return __ldcs(p);
}

__global__ __launch_bounds__(256, 8)
void ginn_input_kernel2(const float* __restrict__ x,
                        const float* __restrict__ W,
                        float* __restrict__ out,
                        int total_outputs) {
    int warp = (blockIdx.x * blockDim.x + threadIdx.x) >> 5;
    int lane = threadIdx.x & 31;

    int o0 = warp * 2;
    int o1 = o0 + 1;
    if (o0 >= total_outputs) return;

    int k0 = o0 & (GK - 1);
    int k1 = o1 & (GK - 1);

    const float4* __restrict__ xp0 =
        reinterpret_cast<const float4*>(x + (size_t)o0 * GN);
    const float4* __restrict__ xp1 =
        reinterpret_cast<const float4*>(x + (size_t)o1 * GN);
    const float4* __restrict__ wp0 =
        reinterpret_cast<const float4*>(W + (size_t)k0 * GN);
    const float4* __restrict__ wp1 =
        reinterpret_cast<const float4*>(W + (size_t)k1 * GN);

    // Front-batch all 8 loads (4 per output): maximal MLP before any FMA.
    float4 xa0 = ldcs4(xp0 + lane);
    float4 xb0 = ldcs4(xp0 + lane + 32);
    float4 xa1 = ldcs4(xp1 + lane);
    float4 xb1 = ldcs4(xp1 + lane + 32);
    float4 wa0 = wp0[lane];
    float4 wb0 = wp0[lane + 32];
    float4 wa1 = wp1[lane];
    float4 wb1 = wp1[lane + 32];

    float s0 = xa0.x * wa0.x;
    s0 = fmaf(xa0.y, wa0.y, s0);
    s0 = fmaf(xa0.z, wa0.z, s0);
    s0 = fmaf(xa0.w, wa0.w, s0);
    s0 = fmaf(xb0.x, wb0.x, s0);
    s0 = fmaf(xb0.y, wb0.y, s0);
    s0 = fmaf(xb0.z, wb0.z, s0);
    s0 = fmaf(xb0.w, wb0.w, s0);

    float s1 = xa1.x * wa1.x;
    s1 = fmaf(xa1.y, wa1.y, s1);
    s1 = fmaf(xa1.z, wa1.z, s1);
    s1 = fmaf(xa1.w, wa1.w, s1);
    s1 = fmaf(xb1.x, wb1.x, s1);
    s1 = fmaf(xb1.y, wb1.y, s1);
    s1 = fmaf(xb1.z, wb1.z, s1);
    s1 = fmaf(xb1.w, wb1.w, s1);

    // Two independent butterfly reductions — they pipeline in the SHFL unit.
    #pragma unroll
    for (int off = 16; off > 0; off >>= 1) {
        s0 += __shfl_xor_sync(0xffffffffu, s0, off);
        s1 += __shfl_xor_sync(0xffffffffu, s1, off);
    }

    if (lane == 0) {
        out[o0] = tanhf(s0);
        if (o1 < total_outputs) out[o1] = tanhf(s1);
    }
}

extern "C" void kernel_launch(void* const* d_in, const int* in_sizes, int n_in,
                              void* d_out, int out_size) {
    const float* x = (const float*)d_in[0];  // [B, K, N] fp32
    const float* W = (const float*)d_in[1];  // [K, N] fp32
    float* out = (float*)d_out;              // [B, K] fp32

    const int total_outputs = out_size;      // B*K = 262144
    const int threads = 256;                 // 8 warps/block, 2 outputs/warp
    const int outputs_per_block = (threads / 32) * 2;
    const int blocks = (total_outputs + outputs_per_block - 1) / outputs_per_block;

    ginn_input_kernel2<<<blocks, threads>>>(x, W, out, total_outputs);
}

// round 3
// speedup vs baseline: 1.0125x; 1.0125x over previous
#include <cuda_runtime.h>

// out[b,k] = tanh( sum_n W[k,n] * x[b,k,n] )
// B=64, K=4096, N=256 (fp32).
// One warp owns one k and holds W[k,:] in REGISTERS (8 floats/lane), so W is
// read from DRAM exactly once per warp instead of 64x through L2. This halves
// total LTS (L2 crossbar) traffic, which R1/R2 profiling showed to be the
// binding ceiling (~12.5 TB/s through LTS vs 6.4 TB/s DRAM).
// 2 warps per k split the b-range (32 b's each); b unrolled by 4 for MLP.

#define GN 256

__global__ __launch_bounds__(256, 4)
void ginn_wreg_kernel(const float* __restrict__ x,
                      const float* __restrict__ W,
                      float* __restrict__ out,
                      int B, int K) {
    int warp = (blockIdx.x * blockDim.x + threadIdx.x) >> 5;
    int lane = threadIdx.x & 31;

    int k    = warp >> 1;        // 2 warps per k
    int half = warp & 1;         // which half of the b-range
    if (k >= K) return;

    // W[k,:] into registers: lane holds elements [lane*4..lane*4+3] and
    // [(lane+32)*4..], i.e. two float4 = 8 floats. Read once from DRAM.
    const float4* __restrict__ wp =
        reinterpret_cast<const float4*>(W + (size_t)k * GN);
    const float4 w0 = wp[lane];
    const float4 w1 = wp[lane + 32];

    const float4* __restrict__ xk =
        reinterpret_cast<const float4*>(x + (size_t)k * GN);
    const size_t bstride4 = (size_t)K * (GN / 4);   // float4 stride per b

    const int bHalf  = B >> 1;          // 32
    const int bBegin = half * bHalf;
    const int bEnd   = bBegin + bHalf;

    for (int b = bBegin; b < bEnd; b += 4) {
        const float4* p0 = xk + (size_t)(b + 0) * bstride4;
        const float4* p1 = xk + (size_t)(b + 1) * bstride4;
        const float4* p2 = xk + (size_t)(b + 2) * bstride4;
        const float4* p3 = xk + (size_t)(b + 3) * bstride4;

        // Front-batch 8 independent 16B loads per lane (streaming hint:
        // x is touched exactly once).
        float4 a0 = __ldcs(p0 + lane);
        float4 c0 = __ldcs(p0 + lane + 32);
        float4 a1 = __ldcs(p1 + lane);
        float4 c1 = __ldcs(p1 + lane + 32);
        float4 a2 = __ldcs(p2 + lane);
        float4 c2 = __ldcs(p2 + lane + 32);
        float4 a3 = __ldcs(p3 + lane);
        float4 c3 = __ldcs(p3 + lane + 32);

        float s0 = a0.x * w0.x;
        s0 = fmaf(a0.y, w0.y, s0); s0 = fmaf(a0.z, w0.z, s0); s0 = fmaf(a0.w, w0.w, s0);
        s0 = fmaf(c0.x, w1.x, s0); s0 = fmaf(c0.y, w1.y, s0);
        s0 = fmaf(c0.z, w1.z, s0); s0 = fmaf(c0.w, w1.w, s0);

        float s1 = a1.x * w0.x;
        s1 = fmaf(a1.y, w0.y, s1); s1 = fmaf(a1.z, w0.z, s1); s1 = fmaf(a1.w, w0.w, s1);
        s1 = fmaf(c1.x, w1.x, s1); s1 = fmaf(c1.y, w1.y, s1);
        s1 = fmaf(c1.z, w1.z, s1); s1 = fmaf(c1.w, w1.w, s1);

        float s2 = a2.x * w0.x;
        s2 = fmaf(a2.y, w0.y, s2); s2 = fmaf(a2.z, w0.z, s2); s2 = fmaf(a2.w, w0.w, s2);
        s2 = fmaf(c2.x, w1.x, s2); s2 = fmaf(c2.y, w1.y, s2);
        s2 = fmaf(c2.z, w1.z, s2); s2 = fmaf(c2.w, w1.w, s2);

        float s3 = a3.x * w0.x;
        s3 = fmaf(a3.y, w0.y, s3); s3 = fmaf(a3.z, w0.z, s3); s3 = fmaf(a3.w, w0.w, s3);
        s3 = fmaf(c3.x, w1.x, s3); s3 = fmaf(c3.y, w1.y, s3);
        s3 = fmaf(c3.z, w1.z, s3); s3 = fmaf(c3.w, w1.w, s3);

        // Four independent butterfly reductions — pipeline in the SHFL unit.
        #pragma unroll
        for (int off = 16; off > 0; off >>= 1) {
            s0 += __shfl_xor_sync(0xffffffffu, s0, off);
            s1 += __shfl_xor_sync(0xffffffffu, s1, off);
            s2 += __shfl_xor_sync(0xffffffffu, s2, off);
            s3 += __shfl_xor_sync(0xffffffffu, s3, off);
        }

        if (lane == 0) {
            out[(size_t)(b + 0) * K + k] = tanhf(s0);
            out[(size_t)(b + 1) * K + k] = tanhf(s1);
            out[(size_t)(b + 2) * K + k] = tanhf(s2);
            out[(size_t)(b + 3) * K + k] = tanhf(s3);
        }
    }
}

extern "C" void kernel_launch(void* const* d_in, const int* in_sizes, int n_in,
                              void* d_out, int out_size) {
    const float* x = (const float*)d_in[0];  // [B, K, N] fp32
    const float* W = (const float*)d_in[1];  // [K, N] fp32
    float* out = (float*)d_out;              // [B, K] fp32

    const int K = in_sizes[1] / GN;          // 4096
    const int B = out_size / K;              // 64

    const int total_warps = K * 2;           // 2 warps per k
    const int threads = 256;                 // 8 warps per block
    const int blocks = (total_warps * 32 + threads - 1) / threads;

    ginn_wreg_kernel<<<blocks, threads>>>(x, W, out, B, K);
}